// round 9
// baseline (speedup 1.0000x reference)
#include <cuda_runtime.h>
#include <cstdint>
#include <math.h>

#define Bc   8
#define Nc   1024
#define OBSc 64
#define HIDc 192
#define Hc   3
#define Dc   64
#define BHc  (Bc*Hc)

#define LDA 36
#define LDB 72
#define JSPLIT 2
#define NTILE_H (Nc / 32 / JSPLIT)
#define NPS 66   // prefix-sum row stride (64 d + 1 scalar + pad)

// Scratch (device globals; no allocation allowed)
__device__ float g_Wh[BHc * Nc * Dc];             // (bh, n, d), pre-rounded tf32
__device__ float g_x [Bc * Nc * HIDc];            // inter-layer activations
__device__ float g_si[BHc * Nc];
__device__ float g_sj[BHc * Nc];
__device__ uint32_t g_adjbits[Nc * 32];           // adjacency bitmask (fallback)
__device__ float g_part[JSPLIT][BHc * Nc * Dc];   // fallback partial O
__device__ float g_pden[JSPLIT][BHc * Nc];        // fallback partial den
__device__ int   g_full;                          // 1 iff adj is all-ones
__device__ float g_sv[BHc * Nc];                  // sorted s_j (ascending)
__device__ int   g_perm[BHc * Nc];                // sort permutation
__device__ float g_PS1[(size_t)BHc * (Nc + 1) * NPS];  // prefix sums (E1 branch)
__device__ float g_PS2[(size_t)BHc * (Nc + 1) * NPS];  // prefix sums (E2 branch)

__device__ __forceinline__ uint32_t tf32u(float x){
    uint32_t u; asm("cvt.rna.tf32.f32 %0, %1;" : "=r"(u) : "f"(x));
    return u;
}
__device__ __forceinline__ void mma8(float* d, uint32_t a0, uint32_t a1, uint32_t a2, uint32_t a3,
                                     uint32_t b0, uint32_t b1){
    asm volatile("mma.sync.aligned.m16n8k8.row.col.f32.tf32.tf32.f32 "
        "{%0,%1,%2,%3}, {%4,%5,%6,%7}, {%8,%9}, {%0,%1,%2,%3};"
        : "+f"(d[0]), "+f"(d[1]), "+f"(d[2]), "+f"(d[3])
        : "r"(a0), "r"(a1), "r"(a2), "r"(a3), "r"(b0), "r"(b1));
}

// ---------------------------------------------------------------------------
__global__ void init_kernel(void){ if (threadIdx.x == 0) g_full = 1; }

__global__ __launch_bounds__(256) void adjbits_kernel(const float* __restrict__ adj)
{
    int w = (blockIdx.x * blockDim.x + threadIdx.x) >> 5;
    int lane = threadIdx.x & 31;
    if (w < Nc * 32){
        float v = adj[(size_t)w * 32 + lane];
        uint32_t m = __ballot_sync(0xffffffffu, v > 0.f);
        if (lane == 0){
            g_adjbits[w] = m;
            if (m != 0xffffffffu) g_full = 0;
        }
    }
}

// ---------------------------------------------------------------------------
// Projection (tf32 mma): Wh = X @ W[h]; fused epilogue emits s_i, s_j.
// ---------------------------------------------------------------------------
template<int K, bool FROM_GX>
__global__ __launch_bounds__(256) void proj_mma(const float* __restrict__ Xe,
                                                const float* __restrict__ W,
                                                const float* __restrict__ av)
{
    __shared__ uint32_t As[128 * LDA];
    __shared__ uint32_t Bs[32 * LDB];
    __shared__ float sa[128];

    int tid = threadIdx.x, lane = tid & 31, wid = tid >> 5;
    int g = lane >> 2, tig = lane & 3, wr0 = wid * 16;
    int row0 = blockIdx.x * 128, h = blockIdx.y;
    const float* X = FROM_GX ? (const float*)g_x : Xe;

    if (tid < 128) sa[tid] = av[h * 128 + tid];

    int ar = tid >> 1, ac = (tid & 1) * 16;
    int bk = tid >> 3, bd = (tid & 7) * 8;

    float acc[8][4] = {};

    #pragma unroll 2
    for (int t = 0; t < K / 32; t++){
        __syncthreads();
        {
            const float* xp = &X[(size_t)(row0 + ar) * K + t * 32 + ac];
            #pragma unroll
            for (int q = 0; q < 4; q++){
                float4 v = *(const float4*)&xp[q * 4];
                As[ar * LDA + ac + q * 4 + 0] = tf32u(v.x);
                As[ar * LDA + ac + q * 4 + 1] = tf32u(v.y);
                As[ar * LDA + ac + q * 4 + 2] = tf32u(v.z);
                As[ar * LDA + ac + q * 4 + 3] = tf32u(v.w);
            }
            const float* wp = &W[(size_t)(h * K + t * 32 + bk) * Dc + bd];
            float4 w0 = *(const float4*)&wp[0];
            float4 w1 = *(const float4*)&wp[4];
            Bs[bk * LDB + bd + 0] = tf32u(w0.x); Bs[bk * LDB + bd + 1] = tf32u(w0.y);
            Bs[bk * LDB + bd + 2] = tf32u(w0.z); Bs[bk * LDB + bd + 3] = tf32u(w0.w);
            Bs[bk * LDB + bd + 4] = tf32u(w1.x); Bs[bk * LDB + bd + 5] = tf32u(w1.y);
            Bs[bk * LDB + bd + 6] = tf32u(w1.z); Bs[bk * LDB + bd + 7] = tf32u(w1.w);
        }
        __syncthreads();
        #pragma unroll
        for (int ks = 0; ks < 4; ks++){
            int ka = ks * 8 + tig;
            uint32_t a0 = As[(wr0 + g    ) * LDA + ka    ];
            uint32_t a1 = As[(wr0 + g + 8) * LDA + ka    ];
            uint32_t a2 = As[(wr0 + g    ) * LDA + ka + 4];
            uint32_t a3 = As[(wr0 + g + 8) * LDA + ka + 4];
            #pragma unroll
            for (int nt = 0; nt < 8; nt++){
                uint32_t b0 = Bs[ ka      * LDB + nt * 8 + g];
                uint32_t b1 = Bs[(ka + 4) * LDB + nt * 8 + g];
                mma8(acc[nt], a0, a1, a2, a3, b0, b1);
            }
        }
    }

    float si0 = 0.f, sj0 = 0.f, si1 = 0.f, sj1 = 0.f;
    #pragma unroll
    for (int nt = 0; nt < 8; nt++){
        #pragma unroll
        for (int c = 0; c < 2; c++){
            int col = nt * 8 + 2 * tig + c;
            float al = sa[col], ar2 = sa[64 + col];
            si0 += acc[nt][c] * al;      sj0 += acc[nt][c] * ar2;
            si1 += acc[nt][2 + c] * al;  sj1 += acc[nt][2 + c] * ar2;
        }
    }
    si0 += __shfl_xor_sync(0xffffffffu, si0, 1); si0 += __shfl_xor_sync(0xffffffffu, si0, 2);
    sj0 += __shfl_xor_sync(0xffffffffu, sj0, 1); sj0 += __shfl_xor_sync(0xffffffffu, sj0, 2);
    si1 += __shfl_xor_sync(0xffffffffu, si1, 1); si1 += __shfl_xor_sync(0xffffffffu, si1, 2);
    sj1 += __shfl_xor_sync(0xffffffffu, sj1, 1); sj1 += __shfl_xor_sync(0xffffffffu, sj1, 2);

    int r = row0 + wr0 + g;
    int b = r >> 10, n = r & (Nc - 1);
    int bh = b * Hc + h;
    if (tig == 0){
        g_si[(size_t)bh * Nc + n] = si0;     g_sj[(size_t)bh * Nc + n] = sj0;
        g_si[(size_t)bh * Nc + n + 8] = si1; g_sj[(size_t)bh * Nc + n + 8] = sj1;
    }
    float* wh0 = &g_Wh[((size_t)bh * Nc + n    ) * Dc];
    float* wh1 = &g_Wh[((size_t)bh * Nc + n + 8) * Dc];
    #pragma unroll
    for (int nt = 0; nt < 8; nt++){
        *(float2*)&wh0[nt * 8 + 2 * tig] =
            make_float2(__uint_as_float(tf32u(acc[nt][0])), __uint_as_float(tf32u(acc[nt][1])));
        *(float2*)&wh1[nt * 8 + 2 * tig] =
            make_float2(__uint_as_float(tf32u(acc[nt][2])), __uint_as_float(tf32u(acc[nt][3])));
    }
}

// ---------------------------------------------------------------------------
// FAST PATH (full adjacency): sort s_j ascending per bh (bitonic in smem).
// ---------------------------------------------------------------------------
__global__ __launch_bounds__(512) void sort_kernel(void)
{
    if (!g_full) return;
    __shared__ float sv[Nc];
    __shared__ int   ix[Nc];
    int bh = blockIdx.x, tid = threadIdx.x;
    for (int i = tid; i < Nc; i += 512){ sv[i] = g_sj[(size_t)bh * Nc + i]; ix[i] = i; }
    __syncthreads();
    for (int k = 2; k <= Nc; k <<= 1){
        for (int j = k >> 1; j > 0; j >>= 1){
            for (int i = tid; i < Nc; i += 512){
                int l = i ^ j;
                if (l > i){
                    bool up = ((i & k) == 0);
                    float a = sv[i], b = sv[l];
                    if (up ? (a > b) : (a < b)){
                        sv[i] = b; sv[l] = a;
                        int t2 = ix[i]; ix[i] = ix[l]; ix[l] = t2;
                    }
                }
            }
            __syncthreads();
        }
    }
    for (int i = tid; i < Nc; i += 512){
        g_sv[(size_t)bh * Nc + i] = sv[i];
        g_perm[(size_t)bh * Nc + i] = ix[i];
    }
}

// ---------------------------------------------------------------------------
// FAST PATH: prefix sums over sorted order.
// PS1[k][c] = sum_{r<k} e^{sv_r} * W(r,c),  PS2 with e^{0.2 sv_r};
// W(r,c) = Wh[perm_r][c] for c<64, 1.0 for c==64 (scalar/denominator column).
// 8 segments x 65 columns; block 544 threads, one block per bh.
// ---------------------------------------------------------------------------
__global__ __launch_bounds__(544) void prefix_kernel(void)
{
    if (!g_full) return;
    __shared__ float E1[Nc], E2[Nc];
    __shared__ int   sp[Nc];
    __shared__ float seg1[8][66], seg2[8][66];
    int bh = blockIdx.x, tid = threadIdx.x;

    for (int k = tid; k < Nc; k += 544){
        float v = g_sv[(size_t)bh * Nc + k];
        E1[k] = expf(v); E2[k] = expf(0.2f * v);
        sp[k] = g_perm[(size_t)bh * Nc + k];
    }
    __syncthreads();

    if (tid < 520){
        int s = tid / 65, c = tid % 65;
        const float* whb = &g_Wh[(size_t)bh * Nc * Dc];
        int base = s * 128;
        float s1 = 0.f, s2 = 0.f;
        for (int u = 0; u < 128; u++){
            int k = base + u;
            float w = (c < 64) ? whb[(size_t)sp[k] * Dc + c] : 1.f;
            s1 += E1[k] * w; s2 += E2[k] * w;
        }
        seg1[s][c] = s1; seg2[s][c] = s2;
    }
    __syncthreads();

    if (tid < 520){
        int s = tid / 65, c = tid % 65;
        float off1 = 0.f, off2 = 0.f;
        for (int q = 0; q < s; q++){ off1 += seg1[q][c]; off2 += seg2[q][c]; }
        const float* whb = &g_Wh[(size_t)bh * Nc * Dc];
        float* P1 = &g_PS1[(size_t)bh * (Nc + 1) * NPS];
        float* P2 = &g_PS2[(size_t)bh * (Nc + 1) * NPS];
        int base = s * 128;
        float r1 = off1, r2 = off2;
        for (int u = 0; u < 128; u++){
            int k = base + u;
            P1[(size_t)k * NPS + c] = r1;
            P2[(size_t)k * NPS + c] = r2;
            float w = (c < 64) ? whb[(size_t)sp[k] * Dc + c] : 1.f;
            r1 += E1[k] * w; r2 += E2[k] * w;
        }
        if (s == 7){
            P1[(size_t)Nc * NPS + c] = r1;
            P2[(size_t)Nc * NPS + c] = r2;
        }
    }
}

// ---------------------------------------------------------------------------
// FAST PATH output: per row i, binary-search split point k, combine prefix
// sums. out_i = (pa1*(T1-PS1[k]) + pa2*PS2[k]) / (same on scalar column).
// One warp per row; 8 rows (same bh) per block; sv cached in smem.
// ---------------------------------------------------------------------------
template<bool ELU, bool TO_GX>
__global__ __launch_bounds__(256) void fastout_kernel(float* __restrict__ out_ext)
{
    if (!g_full) return;
    __shared__ float ssv[Nc];
    int tid = threadIdx.x, lane = tid & 31, wid = tid >> 5;
    int row0 = blockIdx.x * 8;
    int bh = row0 >> 10;
    for (int i = tid; i < Nc; i += 256) ssv[i] = g_sv[(size_t)bh * Nc + i];
    __syncthreads();

    int row = row0 + wid;
    int n = row & (Nc - 1);
    float s_i = g_si[row];
    float smax = ssv[Nc - 1];
    float e = s_i + smax;
    float m = e > 0.f ? e : 0.2f * e;
    float pa1 = expf(s_i - m), pa2 = expf(0.2f * s_i - m);

    // first index with sv[k] > -s_i  (ascending)
    float t = -s_i;
    int lo = 0, hi = Nc;
    while (lo < hi){
        int mid = (lo + hi) >> 1;
        if (ssv[mid] > t) hi = mid; else lo = mid + 1;
    }
    int k = lo;

    const float* P1 = &g_PS1[((size_t)bh * (Nc + 1) + k) * NPS];
    const float* P2 = &g_PS2[((size_t)bh * (Nc + 1) + k) * NPS];
    const float* T1 = &g_PS1[((size_t)bh * (Nc + 1) + Nc) * NPS];

    float den = pa1 * (T1[64] - P1[64]) + pa2 * P2[64];
    float inv = 1.f / den;

    float2 p1 = *(const float2*)&P1[lane * 2];
    float2 p2 = *(const float2*)&P2[lane * 2];
    float2 t1 = *(const float2*)&T1[lane * 2];
    float v0 = (pa1 * (t1.x - p1.x) + pa2 * p2.x) * inv;
    float v1 = (pa1 * (t1.y - p1.y) + pa2 * p2.y) * inv;
    if (ELU){
        v0 = v0 > 0.f ? v0 : expm1f(v0);
        v1 = v1 > 0.f ? v1 : expm1f(v1);
    }
    int b = bh / Hc, hh = bh % Hc;
    float* op = (TO_GX ? (float*)g_x : out_ext) + (size_t)(b * Nc + n) * HIDc + hh * Dc;
    *(float2*)&op[lane * 2] = make_float2(v0, v1);
}

// ---------------------------------------------------------------------------
// FALLBACK (general adjacency): R8 j-split attention + combine.
// ---------------------------------------------------------------------------
__global__ __launch_bounds__(256) void attn_frag(void)
{
    if (g_full) return;
    __shared__ __align__(16) float4 jtab[Nc / JSPLIT];
    __shared__ float sil[128], A1v[128], A2v[128], red[8];
    __shared__ __align__(16) uint32_t wsf[2][32 * 64];

    int tid = threadIdx.x, lane = tid & 31, wid = tid >> 5;
    int g = lane >> 2, tig = lane & 3, wr0 = wid * 16;
    int r0 = wr0 + g, r1 = r0 + 8;
    int bh = blockIdx.y, i0 = blockIdx.x * 128;
    int jh = blockIdx.z, jbase = jh * (Nc / JSPLIT);

    const float* sjg = &g_sj[(size_t)bh * Nc];
    const float* sig = &g_si[(size_t)bh * Nc];

    float lmax = -3.0e38f;
    for (int j = tid; j < Nc; j += 256) lmax = fmaxf(lmax, sjg[j]);
    #pragma unroll
    for (int o = 16; o; o >>= 1) lmax = fmaxf(lmax, __shfl_xor_sync(0xffffffffu, lmax, o));
    if (lane == 0) red[wid] = lmax;
    __syncthreads();
    float smax = red[0];
    #pragma unroll
    for (int w2 = 1; w2 < 8; w2++) smax = fmaxf(smax, red[w2]);
    for (int j = tid; j < Nc / JSPLIT; j += 256){
        float v = sjg[jbase + j];
        jtab[j].x = v; jtab[j].y = expf(v); jtab[j].z = expf(0.2f * v);
    }
    if (tid < 128){
        float s = sig[i0 + tid]; sil[tid] = s;
        float e = s + smax; float m = e > 0.f ? e : 0.2f * e;
        A1v[tid] = expf(s - m); A2v[tid] = expf(0.2f * s - m);
    }
    __syncthreads();

    float psil0 = sil[r0], pa10 = A1v[r0], pa20 = A2v[r0];
    float psil1 = sil[r1], pa11 = A1v[r1], pa21 = A2v[r1];
    const uint32_t* bits0 = &g_adjbits[(size_t)(i0 + r0) * 32 + jh * NTILE_H];
    const uint32_t* bits1 = &g_adjbits[(size_t)(i0 + r1) * 32 + jh * NTILE_H];

    int sk = tid >> 3, snt = tid & 7;
    const float* wsrc = &g_Wh[((size_t)bh * Nc + jbase + sk) * Dc + snt * 8];
    int slot_w0 = (sk & 3) << 1;

    float acc[8][4] = {};
    float d0 = 0.f, d1 = 0.f;

    float4 vaN, vbN;
    {
        float4 va = *(const float4*)&wsrc[0];
        float4 vb = *(const float4*)&wsrc[4];
        float v[8] = {va.x, va.y, va.z, va.w, vb.x, vb.y, vb.z, vb.w};
        #pragma unroll
        for (int gc = 0; gc < 8; gc++)
            wsf[0][sk * 64 + ((gc ^ slot_w0) << 3) + snt] = __float_as_uint(v[gc]);
    }
    vaN = *(const float4*)&wsrc[(size_t)32 * Dc];
    vbN = *(const float4*)&wsrc[(size_t)32 * Dc + 4];
    uint32_t wA_c = bits0[0], wB_c = bits1[0];
    uint32_t wA_n = bits0[1], wB_n = bits1[1];
    __syncthreads();

    for (int t = 0; t < NTILE_H; t++){
        float4 va2 = make_float4(0,0,0,0), vb2 = va2;
        uint32_t wA2 = 0, wB2 = 0;
        if (t + 2 < NTILE_H){
            va2 = *(const float4*)&wsrc[(size_t)(t + 2) * 32 * Dc];
            vb2 = *(const float4*)&wsrc[(size_t)(t + 2) * 32 * Dc + 4];
            wA2 = bits0[t + 2]; wB2 = bits1[t + 2];
        }
        if (t + 1 < NTILE_H){
            float v[8] = {vaN.x, vaN.y, vaN.z, vaN.w, vbN.x, vbN.y, vbN.z, vbN.w};
            uint32_t* W = wsf[(t + 1) & 1];
            #pragma unroll
            for (int gc = 0; gc < 8; gc++)
                W[sk * 64 + ((gc ^ slot_w0) << 3) + snt] = __float_as_uint(v[gc]);
        }
        const uint32_t* W = wsf[t & 1];
        int slot_r = g ^ (tig << 1);
        #pragma unroll
        for (int ks = 0; ks < 4; ks++){
            int jb = t * 32 + ks * 8;
            float4 t0 = jtab[jb + tig];
            float4 t1 = jtab[jb + tig + 4];
            int sh = ks * 8 + tig;
            float p0 = (psil0 + t0.x > 0.f) ? pa10 * t0.y : pa20 * t0.z; if (!((wA_c >> sh) & 1))       p0 = 0.f;
            float p1 = (psil1 + t0.x > 0.f) ? pa11 * t0.y : pa21 * t0.z; if (!((wB_c >> sh) & 1))       p1 = 0.f;
            float p2 = (psil0 + t1.x > 0.f) ? pa10 * t1.y : pa20 * t1.z; if (!((wA_c >> (sh + 4)) & 1)) p2 = 0.f;
            float p3 = (psil1 + t1.x > 0.f) ? pa11 * t1.y : pa21 * t1.z; if (!((wB_c >> (sh + 4)) & 1)) p3 = 0.f;
            uint32_t a0 = tf32u(p0), a1 = tf32u(p1), a2 = tf32u(p2), a3 = tf32u(p3);
            d0 += __uint_as_float(a0) + __uint_as_float(a2);
            d1 += __uint_as_float(a1) + __uint_as_float(a3);
            const uint32_t* br0 = &W[ sh      * 64 + slot_r * 8];
            const uint32_t* br1 = &W[(sh + 4) * 64 + slot_r * 8];
            uint4 b00 = *(const uint4*)br0;
            uint4 b01 = *(const uint4*)(br0 + 4);
            uint4 b10 = *(const uint4*)br1;
            uint4 b11 = *(const uint4*)(br1 + 4);
            mma8(acc[0], a0, a1, a2, a3, b00.x, b10.x);
            mma8(acc[1], a0, a1, a2, a3, b00.y, b10.y);
            mma8(acc[2], a0, a1, a2, a3, b00.z, b10.z);
            mma8(acc[3], a0, a1, a2, a3, b00.w, b10.w);
            mma8(acc[4], a0, a1, a2, a3, b01.x, b11.x);
            mma8(acc[5], a0, a1, a2, a3, b01.y, b11.y);
            mma8(acc[6], a0, a1, a2, a3, b01.z, b11.z);
            mma8(acc[7], a0, a1, a2, a3, b01.w, b11.w);
        }
        vaN = va2; vbN = vb2;
        wA_c = wA_n; wB_c = wB_n; wA_n = wA2; wB_n = wB2;
        __syncthreads();
    }

    d0 += __shfl_xor_sync(0xffffffffu, d0, 1); d0 += __shfl_xor_sync(0xffffffffu, d0, 2);
    d1 += __shfl_xor_sync(0xffffffffu, d1, 1); d1 += __shfl_xor_sync(0xffffffffu, d1, 2);

    int n = i0 + r0;
    if (tig == 0){
        g_pden[jh][(size_t)bh * Nc + n]     = d0;
        g_pden[jh][(size_t)bh * Nc + n + 8] = d1;
    }
    float* p0o = &g_part[jh][((size_t)bh * Nc + n    ) * Dc];
    float* p1o = &g_part[jh][((size_t)bh * Nc + n + 8) * Dc];
    #pragma unroll
    for (int nt = 0; nt < 8; nt++){
        *(float2*)&p0o[nt * 8 + 2 * tig] = make_float2(acc[nt][0], acc[nt][1]);
        *(float2*)&p1o[nt * 8 + 2 * tig] = make_float2(acc[nt][2], acc[nt][3]);
    }
}

template<bool ELU, bool TO_GX>
__global__ __launch_bounds__(256) void combine_kernel(float* __restrict__ out_ext)
{
    if (g_full) return;
    int row = blockIdx.x * 8 + (threadIdx.x >> 5);
    int lane = threadIdx.x & 31;
    int bh = row >> 10, n = row & (Nc - 1);
    float inv = 1.f / (g_pden[0][row] + g_pden[1][row]);
    const float* p0 = &g_part[0][(size_t)row * Dc];
    const float* p1 = &g_part[1][(size_t)row * Dc];
    int b = bh / Hc, hh = bh % Hc;
    float* op = (TO_GX ? (float*)g_x : out_ext) + (size_t)(b * Nc + n) * HIDc + hh * Dc;
    float2 u0 = *(const float2*)&p0[lane * 2];
    float2 u1 = *(const float2*)&p1[lane * 2];
    float v0 = (u0.x + u1.x) * inv;
    float v1 = (u0.y + u1.y) * inv;
    if (ELU){
        v0 = v0 > 0.f ? v0 : expm1f(v0);
        v1 = v1 > 0.f ? v1 : expm1f(v1);
    }
    *(float2*)&op[lane * 2] = make_float2(v0, v1);
}

// ---------------------------------------------------------------------------
extern "C" void kernel_launch(void* const* d_in, const int* in_sizes, int n_in,
                              void* d_out, int out_size)
{
    const float* h   = (const float*)d_in[0];
    const float* adj = (const float*)d_in[1];
    const float* W1  = (const float*)d_in[2];
    const float* a1  = (const float*)d_in[3];
    const float* W2  = (const float*)d_in[4];
    const float* a2  = (const float*)d_in[5];
    float* out = (float*)d_out;

    dim3 projGrid(Bc * Nc / 128, Hc);        // (64, 3)
    dim3 attnGrid(Nc / 128, BHc, JSPLIT);    // fallback grid
    int rowBlocks = BHc * Nc / 8;            // 3072

    init_kernel<<<1, 32>>>();
    adjbits_kernel<<<(Nc * 32 * 32) / 256, 256>>>(adj);

    // Layer 1
    proj_mma<OBSc, false><<<projGrid, 256>>>(h, W1, a1);
    sort_kernel<<<BHc, 512>>>();
    prefix_kernel<<<BHc, 544>>>();
    fastout_kernel<true, true><<<rowBlocks, 256>>>(nullptr);
    attn_frag<<<attnGrid, 256>>>();                     // no-op when full
    combine_kernel<true, true><<<rowBlocks, 256>>>(nullptr);

    // Layer 2
    proj_mma<HIDc, true ><<<projGrid, 256>>>(nullptr, W2, a2);
    sort_kernel<<<BHc, 512>>>();
    prefix_kernel<<<BHc, 544>>>();
    fastout_kernel<false, false><<<rowBlocks, 256>>>(out);
    attn_frag<<<attnGrid, 256>>>();                     // no-op when full
    combine_kernel<false, false><<<rowBlocks, 256>>>(out);
}

// round 10
// speedup vs baseline: 1.4577x; 1.4577x over previous
#include <cuda_runtime.h>
#include <cstdint>
#include <math.h>

#define Bc   8
#define Nc   1024
#define OBSc 64
#define HIDc 192
#define Hc   3
#define Dc   64
#define BHc  (Bc*Hc)

#define LDA 36
#define LDB 72
#define JSPLIT 2
#define NTILE_H (Nc / 32 / JSPLIT)
#define NPS 68   // prefix-sum row stride (64 d + 1 scalar + 3 pad, 16B-aligned)

// Scratch (device globals; no allocation allowed)
__device__ float g_Wh[BHc * Nc * Dc];             // (bh, n, d), pre-rounded tf32
__device__ float g_x [Bc * Nc * HIDc];            // inter-layer activations
__device__ float g_si[BHc * Nc];
__device__ float g_sj[BHc * Nc];
__device__ uint32_t g_adjbits[Nc * 32];           // adjacency bitmask (fallback)
__device__ float g_part[JSPLIT][BHc * Nc * Dc];   // fallback partial O
__device__ float g_pden[JSPLIT][BHc * Nc];        // fallback partial den
__device__ int   g_full;                          // 1 iff adj is all-ones
__device__ int   g_krank[BHc * Nc];               // split index per row
__device__ float g_smax[BHc];                     // max s_j per bh
__device__ float g_PS1[(size_t)BHc * (Nc + 1) * NPS];
__device__ float g_PS2[(size_t)BHc * (Nc + 1) * NPS];

__device__ __forceinline__ uint32_t tf32u(float x){
    uint32_t u; asm("cvt.rna.tf32.f32 %0, %1;" : "=r"(u) : "f"(x));
    return u;
}
__device__ __forceinline__ void mma8(float* d, uint32_t a0, uint32_t a1, uint32_t a2, uint32_t a3,
                                     uint32_t b0, uint32_t b1){
    asm volatile("mma.sync.aligned.m16n8k8.row.col.f32.tf32.tf32.f32 "
        "{%0,%1,%2,%3}, {%4,%5,%6,%7}, {%8,%9}, {%0,%1,%2,%3};"
        : "+f"(d[0]), "+f"(d[1]), "+f"(d[2]), "+f"(d[3])
        : "r"(a0), "r"(a1), "r"(a2), "r"(a3), "r"(b0), "r"(b1));
}

// ---------------------------------------------------------------------------
__global__ void init_kernel(void){ if (threadIdx.x == 0) g_full = 1; }

__global__ __launch_bounds__(256) void adjbits_kernel(const float* __restrict__ adj)
{
    int w = (blockIdx.x * blockDim.x + threadIdx.x) >> 5;
    int lane = threadIdx.x & 31;
    if (w < Nc * 32){
        float v = adj[(size_t)w * 32 + lane];
        uint32_t m = __ballot_sync(0xffffffffu, v > 0.f);
        if (lane == 0){
            g_adjbits[w] = m;
            if (m != 0xffffffffu) g_full = 0;
        }
    }
}

// ---------------------------------------------------------------------------
// Projection (tf32 mma): Wh = X @ W[h]; fused epilogue emits s_i, s_j.
// ---------------------------------------------------------------------------
template<int K, bool FROM_GX>
__global__ __launch_bounds__(256) void proj_mma(const float* __restrict__ Xe,
                                                const float* __restrict__ W,
                                                const float* __restrict__ av)
{
    __shared__ uint32_t As[128 * LDA];
    __shared__ uint32_t Bs[32 * LDB];
    __shared__ float sa[128];

    int tid = threadIdx.x, lane = tid & 31, wid = tid >> 5;
    int g = lane >> 2, tig = lane & 3, wr0 = wid * 16;
    int row0 = blockIdx.x * 128, h = blockIdx.y;
    const float* X = FROM_GX ? (const float*)g_x : Xe;

    if (tid < 128) sa[tid] = av[h * 128 + tid];

    int ar = tid >> 1, ac = (tid & 1) * 16;
    int bk = tid >> 3, bd = (tid & 7) * 8;

    float acc[8][4] = {};

    #pragma unroll 2
    for (int t = 0; t < K / 32; t++){
        __syncthreads();
        {
            const float* xp = &X[(size_t)(row0 + ar) * K + t * 32 + ac];
            #pragma unroll
            for (int q = 0; q < 4; q++){
                float4 v = *(const float4*)&xp[q * 4];
                As[ar * LDA + ac + q * 4 + 0] = tf32u(v.x);
                As[ar * LDA + ac + q * 4 + 1] = tf32u(v.y);
                As[ar * LDA + ac + q * 4 + 2] = tf32u(v.z);
                As[ar * LDA + ac + q * 4 + 3] = tf32u(v.w);
            }
            const float* wp = &W[(size_t)(h * K + t * 32 + bk) * Dc + bd];
            float4 w0 = *(const float4*)&wp[0];
            float4 w1 = *(const float4*)&wp[4];
            Bs[bk * LDB + bd + 0] = tf32u(w0.x); Bs[bk * LDB + bd + 1] = tf32u(w0.y);
            Bs[bk * LDB + bd + 2] = tf32u(w0.z); Bs[bk * LDB + bd + 3] = tf32u(w0.w);
            Bs[bk * LDB + bd + 4] = tf32u(w1.x); Bs[bk * LDB + bd + 5] = tf32u(w1.y);
            Bs[bk * LDB + bd + 6] = tf32u(w1.z); Bs[bk * LDB + bd + 7] = tf32u(w1.w);
        }
        __syncthreads();
        #pragma unroll
        for (int ks = 0; ks < 4; ks++){
            int ka = ks * 8 + tig;
            uint32_t a0 = As[(wr0 + g    ) * LDA + ka    ];
            uint32_t a1 = As[(wr0 + g + 8) * LDA + ka    ];
            uint32_t a2 = As[(wr0 + g    ) * LDA + ka + 4];
            uint32_t a3 = As[(wr0 + g + 8) * LDA + ka + 4];
            #pragma unroll
            for (int nt = 0; nt < 8; nt++){
                uint32_t b0 = Bs[ ka      * LDB + nt * 8 + g];
                uint32_t b1 = Bs[(ka + 4) * LDB + nt * 8 + g];
                mma8(acc[nt], a0, a1, a2, a3, b0, b1);
            }
        }
    }

    float si0 = 0.f, sj0 = 0.f, si1 = 0.f, sj1 = 0.f;
    #pragma unroll
    for (int nt = 0; nt < 8; nt++){
        #pragma unroll
        for (int c = 0; c < 2; c++){
            int col = nt * 8 + 2 * tig + c;
            float al = sa[col], ar2 = sa[64 + col];
            si0 += acc[nt][c] * al;      sj0 += acc[nt][c] * ar2;
            si1 += acc[nt][2 + c] * al;  sj1 += acc[nt][2 + c] * ar2;
        }
    }
    si0 += __shfl_xor_sync(0xffffffffu, si0, 1); si0 += __shfl_xor_sync(0xffffffffu, si0, 2);
    sj0 += __shfl_xor_sync(0xffffffffu, sj0, 1); sj0 += __shfl_xor_sync(0xffffffffu, sj0, 2);
    si1 += __shfl_xor_sync(0xffffffffu, si1, 1); si1 += __shfl_xor_sync(0xffffffffu, si1, 2);
    sj1 += __shfl_xor_sync(0xffffffffu, sj1, 1); sj1 += __shfl_xor_sync(0xffffffffu, sj1, 2);

    int r = row0 + wr0 + g;
    int b = r >> 10, n = r & (Nc - 1);
    int bh = b * Hc + h;
    if (tig == 0){
        g_si[(size_t)bh * Nc + n] = si0;     g_sj[(size_t)bh * Nc + n] = sj0;
        g_si[(size_t)bh * Nc + n + 8] = si1; g_sj[(size_t)bh * Nc + n + 8] = sj1;
    }
    float* wh0 = &g_Wh[((size_t)bh * Nc + n    ) * Dc];
    float* wh1 = &g_Wh[((size_t)bh * Nc + n + 8) * Dc];
    #pragma unroll
    for (int nt = 0; nt < 8; nt++){
        *(float2*)&wh0[nt * 8 + 2 * tig] =
            make_float2(__uint_as_float(tf32u(acc[nt][0])), __uint_as_float(tf32u(acc[nt][1])));
        *(float2*)&wh1[nt * 8 + 2 * tig] =
            make_float2(__uint_as_float(tf32u(acc[nt][2])), __uint_as_float(tf32u(acc[nt][3])));
    }
}

// ---------------------------------------------------------------------------
// FAST PATH fused kernel: warp-bitonic + ranking-merge sort of s_j, split
// ranks k_i, E tables, and float4-gather prefix sums. One block per bh.
// ---------------------------------------------------------------------------
__global__ __launch_bounds__(1024) void sortprefix_kernel(void)
{
    if (!g_full) return;
    __shared__ float va[Nc], vb[Nc];
    __shared__ int   ia[Nc], ib[Nc];
    __shared__ float E1[Nc], E2[Nc];
    __shared__ float seg1[16][NPS], seg2[16][NPS];

    int bh = blockIdx.x, tid = threadIdx.x, lane = tid & 31;

    // 1) load + in-warp bitonic sort (ascending by (value, index))
    float v = g_sj[(size_t)bh * Nc + tid];
    int   ii = tid;
    #pragma unroll
    for (int k = 2; k <= 32; k <<= 1){
        #pragma unroll
        for (int j = k >> 1; j > 0; j >>= 1){
            float ov = __shfl_xor_sync(0xffffffffu, v, j);
            int   oi = __shfl_xor_sync(0xffffffffu, ii, j);
            bool keepLarger = (((lane & k) == 0) == ((lane & j) != 0));
            bool gt = (v > ov) || (v == ov && ii > oi);
            if (keepLarger ? !gt : gt){ v = ov; ii = oi; }
        }
    }
    va[tid] = v; ia[tid] = ii;
    __syncthreads();

    // 2) 5 merge rounds by ranking (ping-pong buffers)
    float *sv_s = va, *sv_d = vb;
    int   *si_s = ia, *si_d = ib;
    for (int L = 32; L < Nc; L <<= 1){
        float mv = sv_s[tid]; int mi = si_s[tid];
        int base = tid & ~((L << 1) - 1);
        int local = tid - base;
        bool inA = local < L;
        int myPos = inA ? local : local - L;
        int sBase = base + (inA ? L : 0);
        int lo = 0, hi = L;
        while (lo < hi){
            int mid = (lo + hi) >> 1;
            float sv2 = sv_s[sBase + mid]; int si2 = si_s[sBase + mid];
            bool lt = (sv2 < mv) || (sv2 == mv && si2 < mi);
            if (lt) lo = mid + 1; else hi = mid;
        }
        sv_d[base + myPos + lo] = mv; si_d[base + myPos + lo] = mi;
        __syncthreads();
        float* tf = sv_s; sv_s = sv_d; sv_d = tf;
        int*   ti = si_s; si_s = si_d; si_d = ti;
    }
    // 5 rounds: final sorted data in vb/ib (sv_s == vb now)

    // 3) split rank per row i:  k = #{j : s_j <= -s_i}
    {
        float t = -g_si[(size_t)bh * Nc + tid];
        int lo = 0, hi = Nc;
        while (lo < hi){
            int mid = (lo + hi) >> 1;
            if (vb[mid] <= t) lo = mid + 1; else hi = mid;
        }
        g_krank[(size_t)bh * Nc + tid] = lo;
    }
    if (tid == 0) g_smax[bh] = vb[Nc - 1];

    // 4) E tables from sorted values
    { float sv2 = vb[tid]; E1[tid] = expf(sv2); E2[tid] = expf(0.2f * sv2); }
    __syncthreads();

    const float* whb = &g_Wh[(size_t)bh * Nc * Dc];

    // 5) Phase A: segment sums (16 segs x 64 elems); float4 over 16 col-quads
    if (tid < 256){
        int seg = tid >> 4, cq = tid & 15, base = seg * 64;
        float4 s1 = make_float4(0,0,0,0), s2 = s1;
        #pragma unroll 8
        for (int u = 0; u < 64; u++){
            int k = base + u;
            float4 w = *(const float4*)&whb[(size_t)ib[k] * Dc + cq * 4];
            float e1 = E1[k], e2 = E2[k];
            s1.x += e1 * w.x; s1.y += e1 * w.y; s1.z += e1 * w.z; s1.w += e1 * w.w;
            s2.x += e2 * w.x; s2.y += e2 * w.y; s2.z += e2 * w.z; s2.w += e2 * w.w;
        }
        *(float4*)&seg1[seg][cq * 4] = s1;
        *(float4*)&seg2[seg][cq * 4] = s2;
    } else if (tid < 272){
        int seg = tid - 256, base = seg * 64;
        float s1 = 0.f, s2 = 0.f;
        #pragma unroll 8
        for (int u = 0; u < 64; u++){ s1 += E1[base + u]; s2 += E2[base + u]; }
        seg1[seg][64] = s1; seg2[seg][64] = s2;
    }
    __syncthreads();

    // 6) Phase B: exclusive scan of segment sums per column
    if (tid < 65){
        float o1 = 0.f, o2 = 0.f;
        #pragma unroll
        for (int s = 0; s < 16; s++){
            float t1 = seg1[s][tid]; seg1[s][tid] = o1; o1 += t1;
            float t2 = seg2[s][tid]; seg2[s][tid] = o2; o2 += t2;
        }
    }
    __syncthreads();

    // 7) Phase C: rescan, write exclusive prefix rows to global
    float* P1g = &g_PS1[(size_t)bh * (Nc + 1) * NPS];
    float* P2g = &g_PS2[(size_t)bh * (Nc + 1) * NPS];
    if (tid < 256){
        int seg = tid >> 4, cq = tid & 15, base = seg * 64;
        float4 r1 = *(float4*)&seg1[seg][cq * 4];
        float4 r2 = *(float4*)&seg2[seg][cq * 4];
        #pragma unroll 8
        for (int u = 0; u < 64; u++){
            int k = base + u;
            *(float4*)&P1g[(size_t)k * NPS + cq * 4] = r1;
            *(float4*)&P2g[(size_t)k * NPS + cq * 4] = r2;
            float4 w = *(const float4*)&whb[(size_t)ib[k] * Dc + cq * 4];
            float e1 = E1[k], e2 = E2[k];
            r1.x += e1 * w.x; r1.y += e1 * w.y; r1.z += e1 * w.z; r1.w += e1 * w.w;
            r2.x += e2 * w.x; r2.y += e2 * w.y; r2.z += e2 * w.z; r2.w += e2 * w.w;
        }
        if (seg == 15){
            *(float4*)&P1g[(size_t)Nc * NPS + cq * 4] = r1;
            *(float4*)&P2g[(size_t)Nc * NPS + cq * 4] = r2;
        }
    } else if (tid < 272){
        int seg = tid - 256, base = seg * 64;
        float r1 = seg1[seg][64], r2 = seg2[seg][64];
        #pragma unroll 8
        for (int u = 0; u < 64; u++){
            int k = base + u;
            P1g[(size_t)k * NPS + 64] = r1;
            P2g[(size_t)k * NPS + 64] = r2;
            r1 += E1[k]; r2 += E2[k];
        }
        if (seg == 15){
            P1g[(size_t)Nc * NPS + 64] = r1;
            P2g[(size_t)Nc * NPS + 64] = r2;
        }
    }
}

// ---------------------------------------------------------------------------
// FAST PATH output: no smem, no barriers. One warp per row.
// ---------------------------------------------------------------------------
template<bool ELU, bool TO_GX>
__global__ __launch_bounds__(256) void fastout_kernel(float* __restrict__ out_ext)
{
    if (!g_full) return;
    int lane = threadIdx.x & 31, wid = threadIdx.x >> 5;
    int row = blockIdx.x * 8 + wid;
    int bh = row >> 10, n = row & (Nc - 1);

    float s_i = g_si[row];
    float smax = g_smax[bh];
    float e = s_i + smax;
    float m = e > 0.f ? e : 0.2f * e;
    float pa1 = expf(s_i - m), pa2 = expf(0.2f * s_i - m);
    int k = g_krank[row];

    const float* P1 = &g_PS1[((size_t)bh * (Nc + 1) + k) * NPS];
    const float* P2 = &g_PS2[((size_t)bh * (Nc + 1) + k) * NPS];
    const float* T1 = &g_PS1[((size_t)bh * (Nc + 1) + Nc) * NPS];

    float den = pa1 * (T1[64] - P1[64]) + pa2 * P2[64];
    float inv = 1.f / den;

    float2 p1 = *(const float2*)&P1[lane * 2];
    float2 p2 = *(const float2*)&P2[lane * 2];
    float2 t1 = *(const float2*)&T1[lane * 2];
    float v0 = (pa1 * (t1.x - p1.x) + pa2 * p2.x) * inv;
    float v1 = (pa1 * (t1.y - p1.y) + pa2 * p2.y) * inv;
    if (ELU){
        v0 = v0 > 0.f ? v0 : expm1f(v0);
        v1 = v1 > 0.f ? v1 : expm1f(v1);
    }
    int b = bh / Hc, hh = bh % Hc;
    float* op = (TO_GX ? (float*)g_x : out_ext) + (size_t)(b * Nc + n) * HIDc + hh * Dc;
    *(float2*)&op[lane * 2] = make_float2(v0, v1);
}

// ---------------------------------------------------------------------------
// FALLBACK (general adjacency): R8 j-split attention + combine.
// ---------------------------------------------------------------------------
__global__ __launch_bounds__(256) void attn_frag(void)
{
    if (g_full) return;
    __shared__ __align__(16) float4 jtab[Nc / JSPLIT];
    __shared__ float sil[128], A1v[128], A2v[128], red[8];
    __shared__ __align__(16) uint32_t wsf[2][32 * 64];

    int tid = threadIdx.x, lane = tid & 31, wid = tid >> 5;
    int g = lane >> 2, tig = lane & 3, wr0 = wid * 16;
    int r0 = wr0 + g, r1 = r0 + 8;
    int bh = blockIdx.y, i0 = blockIdx.x * 128;
    int jh = blockIdx.z, jbase = jh * (Nc / JSPLIT);

    const float* sjg = &g_sj[(size_t)bh * Nc];
    const float* sig = &g_si[(size_t)bh * Nc];

    float lmax = -3.0e38f;
    for (int j = tid; j < Nc; j += 256) lmax = fmaxf(lmax, sjg[j]);
    #pragma unroll
    for (int o = 16; o; o >>= 1) lmax = fmaxf(lmax, __shfl_xor_sync(0xffffffffu, lmax, o));
    if (lane == 0) red[wid] = lmax;
    __syncthreads();
    float smax = red[0];
    #pragma unroll
    for (int w2 = 1; w2 < 8; w2++) smax = fmaxf(smax, red[w2]);
    for (int j = tid; j < Nc / JSPLIT; j += 256){
        float v = sjg[jbase + j];
        jtab[j].x = v; jtab[j].y = expf(v); jtab[j].z = expf(0.2f * v);
    }
    if (tid < 128){
        float s = sig[i0 + tid]; sil[tid] = s;
        float e = s + smax; float m = e > 0.f ? e : 0.2f * e;
        A1v[tid] = expf(s - m); A2v[tid] = expf(0.2f * s - m);
    }
    __syncthreads();

    float psil0 = sil[r0], pa10 = A1v[r0], pa20 = A2v[r0];
    float psil1 = sil[r1], pa11 = A1v[r1], pa21 = A2v[r1];
    const uint32_t* bits0 = &g_adjbits[(size_t)(i0 + r0) * 32 + jh * NTILE_H];
    const uint32_t* bits1 = &g_adjbits[(size_t)(i0 + r1) * 32 + jh * NTILE_H];

    int sk = tid >> 3, snt = tid & 7;
    const float* wsrc = &g_Wh[((size_t)bh * Nc + jbase + sk) * Dc + snt * 8];
    int slot_w0 = (sk & 3) << 1;

    float acc[8][4] = {};
    float d0 = 0.f, d1 = 0.f;

    float4 vaN, vbN;
    {
        float4 va = *(const float4*)&wsrc[0];
        float4 vb = *(const float4*)&wsrc[4];
        float v[8] = {va.x, va.y, va.z, va.w, vb.x, vb.y, vb.z, vb.w};
        #pragma unroll
        for (int gc = 0; gc < 8; gc++)
            wsf[0][sk * 64 + ((gc ^ slot_w0) << 3) + snt] = __float_as_uint(v[gc]);
    }
    vaN = *(const float4*)&wsrc[(size_t)32 * Dc];
    vbN = *(const float4*)&wsrc[(size_t)32 * Dc + 4];
    uint32_t wA_c = bits0[0], wB_c = bits1[0];
    uint32_t wA_n = bits0[1], wB_n = bits1[1];
    __syncthreads();

    for (int t = 0; t < NTILE_H; t++){
        float4 va2 = make_float4(0,0,0,0), vb2 = va2;
        uint32_t wA2 = 0, wB2 = 0;
        if (t + 2 < NTILE_H){
            va2 = *(const float4*)&wsrc[(size_t)(t + 2) * 32 * Dc];
            vb2 = *(const float4*)&wsrc[(size_t)(t + 2) * 32 * Dc + 4];
            wA2 = bits0[t + 2]; wB2 = bits1[t + 2];
        }
        if (t + 1 < NTILE_H){
            float v[8] = {vaN.x, vaN.y, vaN.z, vaN.w, vbN.x, vbN.y, vbN.z, vbN.w};
            uint32_t* W = wsf[(t + 1) & 1];
            #pragma unroll
            for (int gc = 0; gc < 8; gc++)
                W[sk * 64 + ((gc ^ slot_w0) << 3) + snt] = __float_as_uint(v[gc]);
        }
        const uint32_t* W = wsf[t & 1];
        int slot_r = g ^ (tig << 1);
        #pragma unroll
        for (int ks = 0; ks < 4; ks++){
            int jb = t * 32 + ks * 8;
            float4 t0 = jtab[jb + tig];
            float4 t1 = jtab[jb + tig + 4];
            int sh = ks * 8 + tig;
            float p0 = (psil0 + t0.x > 0.f) ? pa10 * t0.y : pa20 * t0.z; if (!((wA_c >> sh) & 1))       p0 = 0.f;
            float p1 = (psil1 + t0.x > 0.f) ? pa11 * t0.y : pa21 * t0.z; if (!((wB_c >> sh) & 1))       p1 = 0.f;
            float p2 = (psil0 + t1.x > 0.f) ? pa10 * t1.y : pa20 * t1.z; if (!((wA_c >> (sh + 4)) & 1)) p2 = 0.f;
            float p3 = (psil1 + t1.x > 0.f) ? pa11 * t1.y : pa21 * t1.z; if (!((wB_c >> (sh + 4)) & 1)) p3 = 0.f;
            uint32_t a0 = tf32u(p0), a1 = tf32u(p1), a2 = tf32u(p2), a3 = tf32u(p3);
            d0 += __uint_as_float(a0) + __uint_as_float(a2);
            d1 += __uint_as_float(a1) + __uint_as_float(a3);
            const uint32_t* br0 = &W[ sh      * 64 + slot_r * 8];
            const uint32_t* br1 = &W[(sh + 4) * 64 + slot_r * 8];
            uint4 b00 = *(const uint4*)br0;
            uint4 b01 = *(const uint4*)(br0 + 4);
            uint4 b10 = *(const uint4*)br1;
            uint4 b11 = *(const uint4*)(br1 + 4);
            mma8(acc[0], a0, a1, a2, a3, b00.x, b10.x);
            mma8(acc[1], a0, a1, a2, a3, b00.y, b10.y);
            mma8(acc[2], a0, a1, a2, a3, b00.z, b10.z);
            mma8(acc[3], a0, a1, a2, a3, b00.w, b10.w);
            mma8(acc[4], a0, a1, a2, a3, b01.x, b11.x);
            mma8(acc[5], a0, a1, a2, a3, b01.y, b11.y);
            mma8(acc[6], a0, a1, a2, a3, b01.z, b11.z);
            mma8(acc[7], a0, a1, a2, a3, b01.w, b11.w);
        }
        vaN = va2; vbN = vb2;
        wA_c = wA_n; wB_c = wB_n; wA_n = wA2; wB_n = wB2;
        __syncthreads();
    }

    d0 += __shfl_xor_sync(0xffffffffu, d0, 1); d0 += __shfl_xor_sync(0xffffffffu, d0, 2);
    d1 += __shfl_xor_sync(0xffffffffu, d1, 1); d1 += __shfl_xor_sync(0xffffffffu, d1, 2);

    int n = i0 + r0;
    if (tig == 0){
        g_pden[jh][(size_t)bh * Nc + n]     = d0;
        g_pden[jh][(size_t)bh * Nc + n + 8] = d1;
    }
    float* p0o = &g_part[jh][((size_t)bh * Nc + n    ) * Dc];
    float* p1o = &g_part[jh][((size_t)bh * Nc + n + 8) * Dc];
    #pragma unroll
    for (int nt = 0; nt < 8; nt++){
        *(float2*)&p0o[nt * 8 + 2 * tig] = make_float2(acc[nt][0], acc[nt][1]);
        *(float2*)&p1o[nt * 8 + 2 * tig] = make_float2(acc[nt][2], acc[nt][3]);
    }
}

template<bool ELU, bool TO_GX>
__global__ __launch_bounds__(256) void combine_kernel(float* __restrict__ out_ext)
{
    if (g_full) return;
    int row = blockIdx.x * 8 + (threadIdx.x >> 5);
    int lane = threadIdx.x & 31;
    int bh = row >> 10, n = row & (Nc - 1);
    float inv = 1.f / (g_pden[0][row] + g_pden[1][row]);
    const float* p0 = &g_part[0][(size_t)row * Dc];
    const float* p1 = &g_part[1][(size_t)row * Dc];
    int b = bh / Hc, hh = bh % Hc;
    float* op = (TO_GX ? (float*)g_x : out_ext) + (size_t)(b * Nc + n) * HIDc + hh * Dc;
    float2 u0 = *(const float2*)&p0[lane * 2];
    float2 u1 = *(const float2*)&p1[lane * 2];
    float v0 = (u0.x + u1.x) * inv;
    float v1 = (u0.y + u1.y) * inv;
    if (ELU){
        v0 = v0 > 0.f ? v0 : expm1f(v0);
        v1 = v1 > 0.f ? v1 : expm1f(v1);
    }
    *(float2*)&op[lane * 2] = make_float2(v0, v1);
}

// ---------------------------------------------------------------------------
extern "C" void kernel_launch(void* const* d_in, const int* in_sizes, int n_in,
                              void* d_out, int out_size)
{
    const float* h   = (const float*)d_in[0];
    const float* adj = (const float*)d_in[1];
    const float* W1  = (const float*)d_in[2];
    const float* a1  = (const float*)d_in[3];
    const float* W2  = (const float*)d_in[4];
    const float* a2  = (const float*)d_in[5];
    float* out = (float*)d_out;

    dim3 projGrid(Bc * Nc / 128, Hc);        // (64, 3)
    dim3 attnGrid(Nc / 128, BHc, JSPLIT);    // fallback grid
    int rowBlocks = BHc * Nc / 8;            // 3072

    init_kernel<<<1, 32>>>();
    adjbits_kernel<<<(Nc * 32 * 32) / 256, 256>>>(adj);

    // Layer 1
    proj_mma<OBSc, false><<<projGrid, 256>>>(h, W1, a1);
    sortprefix_kernel<<<BHc, 1024>>>();
    fastout_kernel<true, true><<<rowBlocks, 256>>>(nullptr);
    attn_frag<<<attnGrid, 256>>>();                     // no-op when full
    combine_kernel<true, true><<<rowBlocks, 256>>>(nullptr);

    // Layer 2
    proj_mma<HIDc, true ><<<projGrid, 256>>>(nullptr, W2, a2);
    sortprefix_kernel<<<BHc, 1024>>>();
    fastout_kernel<false, false><<<rowBlocks, 256>>>(out);
    attn_frag<<<attnGrid, 256>>>();                     // no-op when full
    combine_kernel<false, false><<<rowBlocks, 256>>>(out);
}

// round 13
// speedup vs baseline: 1.9229x; 1.3191x over previous
#include <cuda_runtime.h>
#include <cstdint>
#include <math.h>

#define Bc   8
#define Nc   1024
#define OBSc 64
#define HIDc 192
#define Hc   3
#define Dc   64
#define BHc  (Bc*Hc)

#define LDA 36
#define LDB 72
#define JSPLIT 2
#define NTILE_H (Nc / 32 / JSPLIT)
#define NPS 68          // row stride: 64 d + 1 scalar + 3 pad (16B-aligned)
#define SEGL 128        // rows per prefix segment
#define NSEG (Nc/SEGL)  // 8

// Scratch (device globals; no allocation allowed)
__device__ float g_Wh[BHc * Nc * Dc];             // (bh, n, d), pre-rounded tf32
__device__ float g_x [Bc * Nc * HIDc];            // inter-layer activations
__device__ float g_si[BHc * Nc];
__device__ float g_sj[BHc * Nc];
__device__ uint32_t g_adjbits[Nc * 32];           // adjacency bitmask (fallback)
__device__ float g_part[JSPLIT][BHc * Nc * Dc];   // fallback partial O
__device__ float g_pden[JSPLIT][BHc * Nc];        // fallback partial den
__device__ int   g_full;                          // 1 iff adj is all-ones
__device__ float g_sv[BHc * Nc];                  // sorted s_j
__device__ int   g_perm[BHc * Nc];                // sort permutation
__device__ int   g_krank[BHc * Nc];               // split index per row
__device__ float g_smax[BHc];
__device__ float g_PSl1[(size_t)BHc * Nc * NPS];  // segment-local excl. prefix
__device__ float g_PSl2[(size_t)BHc * Nc * NPS];
__device__ float g_segtot1[BHc * NSEG * NPS];
__device__ float g_segtot2[BHc * NSEG * NPS];
__device__ float g_segoff1[BHc * (NSEG + 1) * NPS];
__device__ float g_segoff2[BHc * (NSEG + 1) * NPS];

__device__ __forceinline__ uint32_t tf32u(float x){
    uint32_t u; asm("cvt.rna.tf32.f32 %0, %1;" : "=r"(u) : "f"(x));
    return u;
}
__device__ __forceinline__ void mma8(float* d, uint32_t a0, uint32_t a1, uint32_t a2, uint32_t a3,
                                     uint32_t b0, uint32_t b1){
    asm volatile("mma.sync.aligned.m16n8k8.row.col.f32.tf32.tf32.f32 "
        "{%0,%1,%2,%3}, {%4,%5,%6,%7}, {%8,%9}, {%0,%1,%2,%3};"
        : "+f"(d[0]), "+f"(d[1]), "+f"(d[2]), "+f"(d[3])
        : "r"(a0), "r"(a1), "r"(a2), "r"(a3), "r"(b0), "r"(b1));
}

// ---------------------------------------------------------------------------
__global__ void init_kernel(void){ if (threadIdx.x == 0) g_full = 1; }

__global__ __launch_bounds__(256) void adjbits_kernel(const float* __restrict__ adj)
{
    int w = (blockIdx.x * blockDim.x + threadIdx.x) >> 5;
    int lane = threadIdx.x & 31;
    if (w < Nc * 32){
        float v = adj[(size_t)w * 32 + lane];
        uint32_t m = __ballot_sync(0xffffffffu, v > 0.f);
        if (lane == 0){
            g_adjbits[w] = m;
            if (m != 0xffffffffu) g_full = 0;
        }
    }
}

// ---------------------------------------------------------------------------
// Projection (tf32 mma): Wh = X @ W[h]; fused epilogue emits s_i, s_j.
// ---------------------------------------------------------------------------
template<int K, bool FROM_GX>
__global__ __launch_bounds__(256) void proj_mma(const float* __restrict__ Xe,
                                                const float* __restrict__ W,
                                                const float* __restrict__ av)
{
    __shared__ uint32_t As[128 * LDA];
    __shared__ uint32_t Bs[32 * LDB];
    __shared__ float sa[128];

    int tid = threadIdx.x, lane = tid & 31, wid = tid >> 5;
    int g = lane >> 2, tig = lane & 3, wr0 = wid * 16;
    int row0 = blockIdx.x * 128, h = blockIdx.y;
    const float* X = FROM_GX ? (const float*)g_x : Xe;

    if (tid < 128) sa[tid] = av[h * 128 + tid];

    int ar = tid >> 1, ac = (tid & 1) * 16;
    int bk = tid >> 3, bd = (tid & 7) * 8;

    float acc[8][4] = {};

    #pragma unroll 2
    for (int t = 0; t < K / 32; t++){
        __syncthreads();
        {
            const float* xp = &X[(size_t)(row0 + ar) * K + t * 32 + ac];
            #pragma unroll
            for (int q = 0; q < 4; q++){
                float4 v = *(const float4*)&xp[q * 4];
                As[ar * LDA + ac + q * 4 + 0] = tf32u(v.x);
                As[ar * LDA + ac + q * 4 + 1] = tf32u(v.y);
                As[ar * LDA + ac + q * 4 + 2] = tf32u(v.z);
                As[ar * LDA + ac + q * 4 + 3] = tf32u(v.w);
            }
            const float* wp = &W[(size_t)(h * K + t * 32 + bk) * Dc + bd];
            float4 w0 = *(const float4*)&wp[0];
            float4 w1 = *(const float4*)&wp[4];
            Bs[bk * LDB + bd + 0] = tf32u(w0.x); Bs[bk * LDB + bd + 1] = tf32u(w0.y);
            Bs[bk * LDB + bd + 2] = tf32u(w0.z); Bs[bk * LDB + bd + 3] = tf32u(w0.w);
            Bs[bk * LDB + bd + 4] = tf32u(w1.x); Bs[bk * LDB + bd + 5] = tf32u(w1.y);
            Bs[bk * LDB + bd + 6] = tf32u(w1.z); Bs[bk * LDB + bd + 7] = tf32u(w1.w);
        }
        __syncthreads();
        #pragma unroll
        for (int ks = 0; ks < 4; ks++){
            int ka = ks * 8 + tig;
            uint32_t a0 = As[(wr0 + g    ) * LDA + ka    ];
            uint32_t a1 = As[(wr0 + g + 8) * LDA + ka    ];
            uint32_t a2 = As[(wr0 + g    ) * LDA + ka + 4];
            uint32_t a3 = As[(wr0 + g + 8) * LDA + ka + 4];
            #pragma unroll
            for (int nt = 0; nt < 8; nt++){
                uint32_t b0 = Bs[ ka      * LDB + nt * 8 + g];
                uint32_t b1 = Bs[(ka + 4) * LDB + nt * 8 + g];
                mma8(acc[nt], a0, a1, a2, a3, b0, b1);
            }
        }
    }

    float si0 = 0.f, sj0 = 0.f, si1 = 0.f, sj1 = 0.f;
    #pragma unroll
    for (int nt = 0; nt < 8; nt++){
        #pragma unroll
        for (int c = 0; c < 2; c++){
            int col = nt * 8 + 2 * tig + c;
            float al = sa[col], ar2 = sa[64 + col];
            si0 += acc[nt][c] * al;      sj0 += acc[nt][c] * ar2;
            si1 += acc[nt][2 + c] * al;  sj1 += acc[nt][2 + c] * ar2;
        }
    }
    si0 += __shfl_xor_sync(0xffffffffu, si0, 1); si0 += __shfl_xor_sync(0xffffffffu, si0, 2);
    sj0 += __shfl_xor_sync(0xffffffffu, sj0, 1); sj0 += __shfl_xor_sync(0xffffffffu, sj0, 2);
    si1 += __shfl_xor_sync(0xffffffffu, si1, 1); si1 += __shfl_xor_sync(0xffffffffu, si1, 2);
    sj1 += __shfl_xor_sync(0xffffffffu, sj1, 1); sj1 += __shfl_xor_sync(0xffffffffu, sj1, 2);

    int r = row0 + wr0 + g;
    int b = r >> 10, n = r & (Nc - 1);
    int bh = b * Hc + h;
    if (tig == 0){
        g_si[(size_t)bh * Nc + n] = si0;     g_sj[(size_t)bh * Nc + n] = sj0;
        g_si[(size_t)bh * Nc + n + 8] = si1; g_sj[(size_t)bh * Nc + n + 8] = sj1;
    }
    float* wh0 = &g_Wh[((size_t)bh * Nc + n    ) * Dc];
    float* wh1 = &g_Wh[((size_t)bh * Nc + n + 8) * Dc];
    #pragma unroll
    for (int nt = 0; nt < 8; nt++){
        *(float2*)&wh0[nt * 8 + 2 * tig] =
            make_float2(__uint_as_float(tf32u(acc[nt][0])), __uint_as_float(tf32u(acc[nt][1])));
        *(float2*)&wh1[nt * 8 + 2 * tig] =
            make_float2(__uint_as_float(tf32u(acc[nt][2])), __uint_as_float(tf32u(acc[nt][3])));
    }
}

// ---------------------------------------------------------------------------
// FAST PATH 1/4: sort s_j per bh (warp bitonic + 5 ranking-merge rounds),
// emit sorted values/permutation, split ranks, smax. One block per bh.
// ---------------------------------------------------------------------------
__global__ __launch_bounds__(1024) void sort_kernel(void)
{
    if (!g_full) return;
    __shared__ float va[Nc], vb[Nc];
    __shared__ int   ia[Nc], ib[Nc];
    int bh = blockIdx.x, tid = threadIdx.x, lane = tid & 31;

    float v = g_sj[(size_t)bh * Nc + tid];
    int   ii = tid;
    #pragma unroll
    for (int k = 2; k <= 32; k <<= 1){
        #pragma unroll
        for (int j = k >> 1; j > 0; j >>= 1){
            float ov = __shfl_xor_sync(0xffffffffu, v, j);
            int   oi = __shfl_xor_sync(0xffffffffu, ii, j);
            bool keepLarger = (((lane & k) == 0) == ((lane & j) != 0));
            bool gt = (v > ov) || (v == ov && ii > oi);
            if (keepLarger ? !gt : gt){ v = ov; ii = oi; }
        }
    }
    va[tid] = v; ia[tid] = ii;
    __syncthreads();

    float *sv_s = va, *sv_d = vb;
    int   *si_s = ia, *si_d = ib;
    for (int L = 32; L < Nc; L <<= 1){
        float mv = sv_s[tid]; int mi = si_s[tid];
        int base = tid & ~((L << 1) - 1);
        int local = tid - base;
        bool inA = local < L;
        int myPos = inA ? local : local - L;
        int sBase = base + (inA ? L : 0);
        int lo = 0, hi = L;
        while (lo < hi){
            int mid = (lo + hi) >> 1;
            float sv2 = sv_s[sBase + mid]; int si2 = si_s[sBase + mid];
            bool lt = (sv2 < mv) || (sv2 == mv && si2 < mi);
            if (lt) lo = mid + 1; else hi = mid;
        }
        sv_d[base + myPos + lo] = mv; si_d[base + myPos + lo] = mi;
        __syncthreads();
        float* tf = sv_s; sv_s = sv_d; sv_d = tf;
        int*   ti = si_s; si_s = si_d; si_d = ti;
    }
    // final sorted in vb/ib

    g_sv[(size_t)bh * Nc + tid] = vb[tid];
    g_perm[(size_t)bh * Nc + tid] = ib[tid];
    {
        float t = -g_si[(size_t)bh * Nc + tid];
        int lo = 0, hi = Nc;
        while (lo < hi){
            int mid = (lo + hi) >> 1;
            if (vb[mid] <= t) lo = mid + 1; else hi = mid;
        }
        g_krank[(size_t)bh * Nc + tid] = lo;
    }
    if (tid == 0) g_smax[bh] = vb[Nc - 1];
}

// ---------------------------------------------------------------------------
// FAST PATH 2/4: per-segment local exclusive prefix + segment totals.
// Grid (NSEG, BHc), 256 threads: thread = (cq 0..15 col-quad, sub 0..15 of
// 8 rows). Chains: 8 (sub sums) + 16 (scan) + 8 (rescan).
// ---------------------------------------------------------------------------
__global__ __launch_bounds__(256) void localscan_kernel(void)
{
    if (!g_full) return;
    __shared__ float e1[SEGL], e2[SEGL];
    __shared__ int   sp[SEGL];
    __shared__ float sub1[16][NPS], sub2[16][NPS];

    int s = blockIdx.x, bh = blockIdx.y, tid = threadIdx.x;
    int kbase = s * SEGL;

    if (tid < SEGL){
        float v = g_sv[(size_t)bh * Nc + kbase + tid];
        e1[tid] = expf(v); e2[tid] = expf(0.2f * v);
        sp[tid] = g_perm[(size_t)bh * Nc + kbase + tid];
    }
    __syncthreads();

    int cq = tid & 15, sub = tid >> 4;
    const float* whb = &g_Wh[(size_t)bh * Nc * Dc];

    float4 w[8];
    #pragma unroll
    for (int u = 0; u < 8; u++)
        w[u] = *(const float4*)&whb[(size_t)sp[sub * 8 + u] * Dc + cq * 4];

    float4 a1 = make_float4(0,0,0,0), a2 = a1;
    float sc1 = 0.f, sc2 = 0.f;
    #pragma unroll
    for (int u = 0; u < 8; u++){
        int k = sub * 8 + u;
        float x1 = e1[k], x2 = e2[k];
        a1.x += x1 * w[u].x; a1.y += x1 * w[u].y; a1.z += x1 * w[u].z; a1.w += x1 * w[u].w;
        a2.x += x2 * w[u].x; a2.y += x2 * w[u].y; a2.z += x2 * w[u].z; a2.w += x2 * w[u].w;
        sc1 += x1; sc2 += x2;
    }
    *(float4*)&sub1[sub][cq * 4] = a1;
    *(float4*)&sub2[sub][cq * 4] = a2;
    if (cq == 0){ sub1[sub][64] = sc1; sub2[sub][64] = sc2; }
    __syncthreads();

    if (tid < 65){
        float o1 = 0.f, o2 = 0.f;
        #pragma unroll
        for (int q = 0; q < 16; q++){
            float t1 = sub1[q][tid]; sub1[q][tid] = o1; o1 += t1;
            float t2 = sub2[q][tid]; sub2[q][tid] = o2; o2 += t2;
        }
        g_segtot1[(bh * NSEG + s) * NPS + tid] = o1;
        g_segtot2[(bh * NSEG + s) * NPS + tid] = o2;
    }
    __syncthreads();

    float4 r1 = *(float4*)&sub1[sub][cq * 4];
    float4 r2 = *(float4*)&sub2[sub][cq * 4];
    float rs1 = sub1[sub][64], rs2 = sub2[sub][64];
    float* P1 = &g_PSl1[((size_t)bh * Nc + kbase) * NPS];
    float* P2 = &g_PSl2[((size_t)bh * Nc + kbase) * NPS];
    #pragma unroll
    for (int u = 0; u < 8; u++){
        int k = sub * 8 + u;
        *(float4*)&P1[(size_t)k * NPS + cq * 4] = r1;
        *(float4*)&P2[(size_t)k * NPS + cq * 4] = r2;
        float x1 = e1[k], x2 = e2[k];
        r1.x += x1 * w[u].x; r1.y += x1 * w[u].y; r1.z += x1 * w[u].z; r1.w += x1 * w[u].w;
        r2.x += x2 * w[u].x; r2.y += x2 * w[u].y; r2.z += x2 * w[u].z; r2.w += x2 * w[u].w;
        if (cq == 0){
            P1[(size_t)k * NPS + 64] = rs1;
            P2[(size_t)k * NPS + 64] = rs2;
            rs1 += x1; rs2 += x2;
        }
    }
}

// ---------------------------------------------------------------------------
// FAST PATH 3/4: scan segment totals -> offsets (row NSEG = grand total).
// ---------------------------------------------------------------------------
__global__ __launch_bounds__(96) void scanoff_kernel(void)
{
    if (!g_full) return;
    int bh = blockIdx.x, c = threadIdx.x;
    if (c >= 65) return;
    float t1[NSEG], t2[NSEG];
    #pragma unroll
    for (int s = 0; s < NSEG; s++){
        t1[s] = g_segtot1[(bh * NSEG + s) * NPS + c];
        t2[s] = g_segtot2[(bh * NSEG + s) * NPS + c];
    }
    float o1 = 0.f, o2 = 0.f;
    #pragma unroll
    for (int s = 0; s < NSEG; s++){
        g_segoff1[(bh * (NSEG + 1) + s) * NPS + c] = o1;
        g_segoff2[(bh * (NSEG + 1) + s) * NPS + c] = o2;
        o1 += t1[s]; o2 += t2[s];
    }
    g_segoff1[(bh * (NSEG + 1) + NSEG) * NPS + c] = o1;
    g_segoff2[(bh * (NSEG + 1) + NSEG) * NPS + c] = o2;
}

// ---------------------------------------------------------------------------
// FAST PATH 4/4 output: PS[k] = segoff[k>>7] + PSlocal[k]; T = segoff[NSEG].
// One warp per row; no smem, no barriers.
// ---------------------------------------------------------------------------
template<bool ELU, bool TO_GX>
__global__ __launch_bounds__(256) void fastout_kernel(float* __restrict__ out_ext)
{
    if (!g_full) return;
    int lane = threadIdx.x & 31, wid = threadIdx.x >> 5;
    int row = blockIdx.x * 8 + wid;
    int bh = row >> 10, n = row & (Nc - 1);

    float s_i = g_si[row];
    float smax = g_smax[bh];
    float e = s_i + smax;
    float m = e > 0.f ? e : 0.2f * e;
    float pa1 = expf(s_i - m), pa2 = expf(0.2f * s_i - m);
    int k = g_krank[row];
    int s = k >> 7;   // k==Nc -> s==NSEG, local part = 0

    const float* SO1 = &g_segoff1[(bh * (NSEG + 1) + s) * NPS];
    const float* SO2 = &g_segoff2[(bh * (NSEG + 1) + s) * NPS];
    const float* T1  = &g_segoff1[(bh * (NSEG + 1) + NSEG) * NPS];

    float2 so1 = *(const float2*)&SO1[lane * 2];
    float2 so2 = *(const float2*)&SO2[lane * 2];
    float2 t1  = *(const float2*)&T1[lane * 2];
    float so1s = SO1[64], so2s = SO2[64], t1s = T1[64];

    float2 pl1 = make_float2(0.f, 0.f), pl2 = pl1;
    float pl1s = 0.f, pl2s = 0.f;
    if (k < Nc){
        const float* P1 = &g_PSl1[((size_t)bh * Nc + k) * NPS];
        const float* P2 = &g_PSl2[((size_t)bh * Nc + k) * NPS];
        pl1 = *(const float2*)&P1[lane * 2];
        pl2 = *(const float2*)&P2[lane * 2];
        pl1s = P1[64]; pl2s = P2[64];
    }

    float ps1s = so1s + pl1s, ps2s = so2s + pl2s;
    float den = pa1 * (t1s - ps1s) + pa2 * ps2s;
    float inv = 1.f / den;

    float v0 = (pa1 * (t1.x - (so1.x + pl1.x)) + pa2 * (so2.x + pl2.x)) * inv;
    float v1 = (pa1 * (t1.y - (so1.y + pl1.y)) + pa2 * (so2.y + pl2.y)) * inv;
    if (ELU){
        v0 = v0 > 0.f ? v0 : expm1f(v0);
        v1 = v1 > 0.f ? v1 : expm1f(v1);
    }
    int b = bh / Hc, hh = bh % Hc;
    float* op = (TO_GX ? (float*)g_x : out_ext) + (size_t)(b * Nc + n) * HIDc + hh * Dc;
    *(float2*)&op[lane * 2] = make_float2(v0, v1);
}

// ---------------------------------------------------------------------------
// FALLBACK (general adjacency): R8 j-split attention + combine.
// ---------------------------------------------------------------------------
__global__ __launch_bounds__(256) void attn_frag(void)
{
    if (g_full) return;
    __shared__ __align__(16) float4 jtab[Nc / JSPLIT];
    __shared__ float sil[128], A1v[128], A2v[128], red[8];
    __shared__ __align__(16) uint32_t wsf[2][32 * 64];

    int tid = threadIdx.x, lane = tid & 31, wid = tid >> 5;
    int g = lane >> 2, tig = lane & 3, wr0 = wid * 16;
    int r0 = wr0 + g, r1 = r0 + 8;
    int bh = blockIdx.y, i0 = blockIdx.x * 128;
    int jh = blockIdx.z, jbase = jh * (Nc / JSPLIT);

    const float* sjg = &g_sj[(size_t)bh * Nc];
    const float* sig = &g_si[(size_t)bh * Nc];

    float lmax = -3.0e38f;
    for (int j = tid; j < Nc; j += 256) lmax = fmaxf(lmax, sjg[j]);
    #pragma unroll
    for (int o = 16; o; o >>= 1) lmax = fmaxf(lmax, __shfl_xor_sync(0xffffffffu, lmax, o));
    if (lane == 0) red[wid] = lmax;
    __syncthreads();
    float smax = red[0];
    #pragma unroll
    for (int w2 = 1; w2 < 8; w2++) smax = fmaxf(smax, red[w2]);
    for (int j = tid; j < Nc / JSPLIT; j += 256){
        float v = sjg[jbase + j];
        jtab[j].x = v; jtab[j].y = expf(v); jtab[j].z = expf(0.2f * v);
    }
    if (tid < 128){
        float s = sig[i0 + tid]; sil[tid] = s;
        float e = s + smax; float m = e > 0.f ? e : 0.2f * e;
        A1v[tid] = expf(s - m); A2v[tid] = expf(0.2f * s - m);
    }
    __syncthreads();

    float psil0 = sil[r0], pa10 = A1v[r0], pa20 = A2v[r0];
    float psil1 = sil[r1], pa11 = A1v[r1], pa21 = A2v[r1];
    const uint32_t* bits0 = &g_adjbits[(size_t)(i0 + r0) * 32 + jh * NTILE_H];
    const uint32_t* bits1 = &g_adjbits[(size_t)(i0 + r1) * 32 + jh * NTILE_H];

    int sk = tid >> 3, snt = tid & 7;
    const float* wsrc = &g_Wh[((size_t)bh * Nc + jbase + sk) * Dc + snt * 8];
    int slot_w0 = (sk & 3) << 1;

    float acc[8][4] = {};
    float d0 = 0.f, d1 = 0.f;

    float4 vaN, vbN;
    {
        float4 va = *(const float4*)&wsrc[0];
        float4 vb = *(const float4*)&wsrc[4];
        float v[8] = {va.x, va.y, va.z, va.w, vb.x, vb.y, vb.z, vb.w};
        #pragma unroll
        for (int gc = 0; gc < 8; gc++)
            wsf[0][sk * 64 + ((gc ^ slot_w0) << 3) + snt] = __float_as_uint(v[gc]);
    }
    vaN = *(const float4*)&wsrc[(size_t)32 * Dc];
    vbN = *(const float4*)&wsrc[(size_t)32 * Dc + 4];
    uint32_t wA_c = bits0[0], wB_c = bits1[0];
    uint32_t wA_n = bits0[1], wB_n = bits1[1];
    __syncthreads();

    for (int t = 0; t < NTILE_H; t++){
        float4 va2 = make_float4(0,0,0,0), vb2 = va2;
        uint32_t wA2 = 0, wB2 = 0;
        if (t + 2 < NTILE_H){
            va2 = *(const float4*)&wsrc[(size_t)(t + 2) * 32 * Dc];
            vb2 = *(const float4*)&wsrc[(size_t)(t + 2) * 32 * Dc + 4];
            wA2 = bits0[t + 2]; wB2 = bits1[t + 2];
        }
        if (t + 1 < NTILE_H){
            float v[8] = {vaN.x, vaN.y, vaN.z, vaN.w, vbN.x, vbN.y, vbN.z, vbN.w};
            uint32_t* W = wsf[(t + 1) & 1];
            #pragma unroll
            for (int gc = 0; gc < 8; gc++)
                W[sk * 64 + ((gc ^ slot_w0) << 3) + snt] = __float_as_uint(v[gc]);
        }
        const uint32_t* W = wsf[t & 1];
        int slot_r = g ^ (tig << 1);
        #pragma unroll
        for (int ks = 0; ks < 4; ks++){
            int jb = t * 32 + ks * 8;
            float4 t0 = jtab[jb + tig];
            float4 t1 = jtab[jb + tig + 4];
            int sh = ks * 8 + tig;
            float p0 = (psil0 + t0.x > 0.f) ? pa10 * t0.y : pa20 * t0.z; if (!((wA_c >> sh) & 1))       p0 = 0.f;
            float p1 = (psil1 + t0.x > 0.f) ? pa11 * t0.y : pa21 * t0.z; if (!((wB_c >> sh) & 1))       p1 = 0.f;
            float p2 = (psil0 + t1.x > 0.f) ? pa10 * t1.y : pa20 * t1.z; if (!((wA_c >> (sh + 4)) & 1)) p2 = 0.f;
            float p3 = (psil1 + t1.x > 0.f) ? pa11 * t1.y : pa21 * t1.z; if (!((wB_c >> (sh + 4)) & 1)) p3 = 0.f;
            uint32_t a0 = tf32u(p0), a1 = tf32u(p1), a2 = tf32u(p2), a3 = tf32u(p3);
            d0 += __uint_as_float(a0) + __uint_as_float(a2);
            d1 += __uint_as_float(a1) + __uint_as_float(a3);
            const uint32_t* br0 = &W[ sh      * 64 + slot_r * 8];
            const uint32_t* br1 = &W[(sh + 4) * 64 + slot_r * 8];
            uint4 b00 = *(const uint4*)br0;
            uint4 b01 = *(const uint4*)(br0 + 4);
            uint4 b10 = *(const uint4*)br1;
            uint4 b11 = *(const uint4*)(br1 + 4);
            mma8(acc[0], a0, a1, a2, a3, b00.x, b10.x);
            mma8(acc[1], a0, a1, a2, a3, b00.y, b10.y);
            mma8(acc[2], a0, a1, a2, a3, b00.z, b10.z);
            mma8(acc[3], a0, a1, a2, a3, b00.w, b10.w);
            mma8(acc[4], a0, a1, a2, a3, b01.x, b11.x);
            mma8(acc[5], a0, a1, a2, a3, b01.y, b11.y);
            mma8(acc[6], a0, a1, a2, a3, b01.z, b11.z);
            mma8(acc[7], a0, a1, a2, a3, b01.w, b11.w);
        }
        vaN = va2; vbN = vb2;
        wA_c = wA_n; wB_c = wB_n; wA_n = wA2; wB_n = wB2;
        __syncthreads();
    }

    d0 += __shfl_xor_sync(0xffffffffu, d0, 1); d0 += __shfl_xor_sync(0xffffffffu, d0, 2);
    d1 += __shfl_xor_sync(0xffffffffu, d1, 1); d1 += __shfl_xor_sync(0xffffffffu, d1, 2);

    int n = i0 + r0;
    if (tig == 0){
        g_pden[jh][(size_t)bh * Nc + n]     = d0;
        g_pden[jh][(size_t)bh * Nc + n + 8] = d1;
    }
    float* p0o = &g_part[jh][((size_t)bh * Nc + n    ) * Dc];
    float* p1o = &g_part[jh][((size_t)bh * Nc + n + 8) * Dc];
    #pragma unroll
    for (int nt = 0; nt < 8; nt++){
        *(float2*)&p0o[nt * 8 + 2 * tig] = make_float2(acc[nt][0], acc[nt][1]);
        *(float2*)&p1o[nt * 8 + 2 * tig] = make_float2(acc[nt][2], acc[nt][3]);
    }
}

template<bool ELU, bool TO_GX>
__global__ __launch_bounds__(256) void combine_kernel(float* __restrict__ out_ext)
{
    if (g_full) return;
    int row = blockIdx.x * 8 + (threadIdx.x >> 5);
    int lane = threadIdx.x & 31;
    int bh = row >> 10, n = row & (Nc - 1);
    float inv = 1.f / (g_pden[0][row] + g_pden[1][row]);
    const float* p0 = &g_part[0][(size_t)row * Dc];
    const float* p1 = &g_part[1][(size_t)row * Dc];
    int b = bh / Hc, hh = bh % Hc;
    float* op = (TO_GX ? (float*)g_x : out_ext) + (size_t)(b * Nc + n) * HIDc + hh * Dc;
    float2 u0 = *(const float2*)&p0[lane * 2];
    float2 u1 = *(const float2*)&p1[lane * 2];
    float v0 = (u0.x + u1.x) * inv;
    float v1 = (u0.y + u1.y) * inv;
    if (ELU){
        v0 = v0 > 0.f ? v0 : expm1f(v0);
        v1 = v1 > 0.f ? v1 : expm1f(v1);
    }
    *(float2*)&op[lane * 2] = make_float2(v0, v1);
}

// ---------------------------------------------------------------------------
extern "C" void kernel_launch(void* const* d_in, const int* in_sizes, int n_in,
                              void* d_out, int out_size)
{
    const float* h   = (const float*)d_in[0];
    const float* adj = (const float*)d_in[1];
    const float* W1  = (const float*)d_in[2];
    const float* a1  = (const float*)d_in[3];
    const float* W2  = (const float*)d_in[4];
    const float* a2  = (const float*)d_in[5];
    float* out = (float*)d_out;

    dim3 projGrid(Bc * Nc / 128, Hc);        // (64, 3)
    dim3 scanGrid(NSEG, BHc);                // (8, 24) = 192
    dim3 attnGrid(Nc / 128, BHc, JSPLIT);    // fallback grid
    int rowBlocks = BHc * Nc / 8;            // 3072

    init_kernel<<<1, 32>>>();
    adjbits_kernel<<<(Nc * 32 * 32) / 256, 256>>>(adj);

    // Layer 1
    proj_mma<OBSc, false><<<projGrid, 256>>>(h, W1, a1);
    sort_kernel<<<BHc, 1024>>>();
    localscan_kernel<<<scanGrid, 256>>>();
    scanoff_kernel<<<BHc, 96>>>();
    fastout_kernel<true, true><<<rowBlocks, 256>>>(nullptr);
    attn_frag<<<attnGrid, 256>>>();                     // no-op when full
    combine_kernel<true, true><<<rowBlocks, 256>>>(nullptr);

    // Layer 2
    proj_mma<HIDc, true ><<<projGrid, 256>>>(nullptr, W2, a2);
    sort_kernel<<<BHc, 1024>>>();
    localscan_kernel<<<scanGrid, 256>>>();
    scanoff_kernel<<<BHc, 96>>>();
    fastout_kernel<false, false><<<rowBlocks, 256>>>(out);
    attn_frag<<<attnGrid, 256>>>();                     // no-op when full
    combine_kernel<false, false><<<rowBlocks, 256>>>(out);
}